// round 4
// baseline (speedup 1.0000x reference)
#include <cuda_runtime.h>
#include <math.h>

#define N_NODES 50000
#define N_EDGES 800000
#define IN_DIM  128
#define HID_DIM 128
#define OUT_DIM 64

typedef unsigned long long ull;

// ---------------- scratch (static device globals; no allocation) ----------------
__device__ float g_dinv[N_NODES];
__device__ int   g_degi[N_NODES];
__device__ int   g_off [N_NODES + 1];
__device__ int   g_cur [N_NODES];
__device__ int   g_bsum[256];
__device__ int   g_col [N_EDGES];
__device__ float g_h   [(size_t)N_NODES * HID_DIM];  // x @ W1 (raw)
__device__ float g_h2  [(size_t)N_NODES * OUT_DIM];  // h1 @ W2 (raw)

// ---------------- f32x2 packed math ----------------
__device__ __forceinline__ ull pack2(float lo, float hi) {
    ull r; asm("mov.b64 %0, {%1, %2};" : "=l"(r) : "f"(lo), "f"(hi)); return r;
}
__device__ __forceinline__ ull fma2(ull a, ull b, ull c) {
    ull d; asm("fma.rn.f32x2 %0, %1, %2, %3;" : "=l"(d) : "l"(a), "l"(b), "l"(c)); return d;
}
__device__ __forceinline__ float2 unpack2(ull p) {
    float2 f; asm("mov.b64 {%0, %1}, %2;" : "=f"(f.x), "=f"(f.y) : "l"(p)); return f;
}

// ---------------- degree / norm / CSR build ----------------
__global__ void k_zero() {
    int i = blockIdx.x * blockDim.x + threadIdx.x;
    if (i < N_NODES) g_degi[i] = 0;
}
__global__ void k_count(const int* __restrict__ dst) {
    int e = blockIdx.x * blockDim.x + threadIdx.x;
    if (e < N_EDGES) atomicAdd(&g_degi[dst[e]], 1);
}
// block-local exclusive scan + dinv fused
__global__ void k_scan1() {
    __shared__ int s[256];
    int i = blockIdx.x * 256 + threadIdx.x;
    int v = (i < N_NODES) ? g_degi[i] : 0;
    if (i < N_NODES) g_dinv[i] = rsqrtf((float)(v + 1));  // +1 self-loop
    s[threadIdx.x] = v;
    __syncthreads();
    for (int d = 1; d < 256; d <<= 1) {
        int t = (threadIdx.x >= d) ? s[threadIdx.x - d] : 0;
        __syncthreads();
        s[threadIdx.x] += t;
        __syncthreads();
    }
    if (i < N_NODES) g_off[i] = s[threadIdx.x] - v;
    if (threadIdx.x == 255) g_bsum[blockIdx.x] = s[255];
}
__global__ void k_scan2(int nblk) {
    __shared__ int s[256];
    int t = threadIdx.x;
    int v = (t < nblk) ? g_bsum[t] : 0;
    s[t] = v;
    __syncthreads();
    for (int d = 1; d < 256; d <<= 1) {
        int u = (t >= d) ? s[t - d] : 0;
        __syncthreads();
        s[t] += u;
        __syncthreads();
    }
    if (t < nblk) g_bsum[t] = s[t] - v;
}
__global__ void k_scan3() {
    int i = blockIdx.x * blockDim.x + threadIdx.x;
    if (i < N_NODES) {
        int o = g_off[i] + g_bsum[i >> 8];
        g_off[i] = o;
        g_cur[i] = o;
    }
    if (i == 0) g_off[N_NODES] = N_EDGES;
}
__global__ void k_fill(const int* __restrict__ src, const int* __restrict__ dst) {
    int e = blockIdx.x * blockDim.x + threadIdx.x;
    if (e < N_EDGES) {
        int p = atomicAdd(&g_cur[dst[e]], 1);
        g_col[p] = src[e];
    }
}

// ---------------- GEMM: Y = X[.,K] @ W[K,N], f32x2, duplicated-x smem -----------
// Block: 256 threads. tx in [0,TX): owns col pairs (2tx, 2tx+1) and (+2*TX).
// ty in [0, 256/TX): owns 8 rows. RB = (256/TX)*8 rows per block.
template <int K, int N, int TX>
__global__ void __launch_bounds__(256, 3)
k_gemm(const float* __restrict__ X, const float* __restrict__ W,
       float* __restrict__ Y) {
    constexpr int TY = 256 / TX;
    constexpr int RB = TY * 8;
    constexpr int NH = N / 2;                 // ull stride per kk in ws
    __shared__ ull   xsd[RB * 32];            // x duplicated pairs [row][kk]
    __shared__ float ws [32 * N];             // w tile [kk][col]

    const int tid = threadIdx.x;
    const int tx = tid % TX, ty = tid / TX;
    const long r0 = (long)blockIdx.x * RB;

    ull acc[8][2];
#pragma unroll
    for (int r = 0; r < 8; r++) { acc[r][0] = 0ull; acc[r][1] = 0ull; }

    for (int k0 = 0; k0 < K; k0 += 32) {
        // xsd tile: RB rows x 32 kk, each elem duplicated {x,x}
        for (int t = tid; t < RB * 8; t += 256) {
            int r = t >> 3, q = t & 7;
            long row = r0 + r; if (row >= N_NODES) row = N_NODES - 1;
            float4 v = __ldg((const float4*)(X + row * K + k0) + q);
            ulonglong2* xp = (ulonglong2*)&xsd[r * 32 + q * 4];
            xp[0] = make_ulonglong2(pack2(v.x, v.x), pack2(v.y, v.y));
            xp[1] = make_ulonglong2(pack2(v.z, v.z), pack2(v.w, v.w));
        }
        // ws tile: 32 x N contiguous slab
        const float4* wsrc = (const float4*)(W + (size_t)k0 * N);
        for (int t = tid; t < 8 * N; t += 256)
            ((float4*)ws)[t] = __ldg(wsrc + t);
        __syncthreads();

        const ull* wsp = (const ull*)ws;
#pragma unroll 4
        for (int kk2 = 0; kk2 < 16; kk2++) {
            ull w0a = wsp[(2 * kk2)     * NH + tx];
            ull w0b = wsp[(2 * kk2)     * NH + tx + TX];
            ull w1a = wsp[(2 * kk2 + 1) * NH + tx];
            ull w1b = wsp[(2 * kk2 + 1) * NH + tx + TX];
#pragma unroll
            for (int r = 0; r < 8; r++) {
                ulonglong2 xp = *(const ulonglong2*)&xsd[(ty * 8 + r) * 32 + 2 * kk2];
                acc[r][0] = fma2(xp.x, w0a, acc[r][0]);
                acc[r][1] = fma2(xp.x, w0b, acc[r][1]);
                acc[r][0] = fma2(xp.y, w1a, acc[r][0]);
                acc[r][1] = fma2(xp.y, w1b, acc[r][1]);
            }
        }
        __syncthreads();
    }

#pragma unroll
    for (int r = 0; r < 8; r++) {
        long row = r0 + ty * 8 + r;
        if (row < N_NODES) {
            float2 f0 = unpack2(acc[r][0]);
            float2 f1 = unpack2(acc[r][1]);
            *(float2*)&Y[row * N + 2 * tx]            = f0;
            *(float2*)&Y[row * N + 2 * (tx + TX)]     = f1;
        }
    }
}

// ---------------- pull aggregation, C=128: warp per node, 2-way unrolled ---------
__global__ void k_pull128(const float* __restrict__ hraw, const float* __restrict__ b,
                          float* __restrict__ out) {
    int w = (blockIdx.x * blockDim.x + threadIdx.x) >> 5;
    if (w >= N_NODES) return;
    int lane = threadIdx.x & 31;
    float din = g_dinv[w];
    float4 h0 = __ldg((const float4*)(hraw + (size_t)w * 128) + lane);
    float4 bv = __ldg((const float4*)b + lane);
    float sl = din * din;
    float4 acc, acc2 = make_float4(0.f, 0.f, 0.f, 0.f);
    acc.x = fmaf(h0.x, sl, bv.x); acc.y = fmaf(h0.y, sl, bv.y);
    acc.z = fmaf(h0.z, sl, bv.z); acc.w = fmaf(h0.w, sl, bv.w);

    int s0 = g_off[w], s1 = g_off[w + 1];
    for (int j0 = s0; j0 < s1; j0 += 32) {
        int jj = j0 + lane;
        int cc = 0; float nd = 0.0f;
        if (jj < s1) { cc = g_col[jj]; nd = g_dinv[cc]; }
        int cnt = min(32, s1 - j0);
        int i = 0;
        for (; i + 2 <= cnt; i += 2) {
            int   sA = __shfl_sync(0xffffffffu, cc, i);
            float nA = __shfl_sync(0xffffffffu, nd, i) * din;
            int   sB = __shfl_sync(0xffffffffu, cc, i + 1);
            float nB = __shfl_sync(0xffffffffu, nd, i + 1) * din;
            float4 hA = __ldg((const float4*)(hraw + (size_t)sA * 128) + lane);
            float4 hB = __ldg((const float4*)(hraw + (size_t)sB * 128) + lane);
            acc.x  = fmaf(hA.x, nA, acc.x);  acc.y  = fmaf(hA.y, nA, acc.y);
            acc.z  = fmaf(hA.z, nA, acc.z);  acc.w  = fmaf(hA.w, nA, acc.w);
            acc2.x = fmaf(hB.x, nB, acc2.x); acc2.y = fmaf(hB.y, nB, acc2.y);
            acc2.z = fmaf(hB.z, nB, acc2.z); acc2.w = fmaf(hB.w, nB, acc2.w);
        }
        if (i < cnt) {
            int   sA = __shfl_sync(0xffffffffu, cc, i);
            float nA = __shfl_sync(0xffffffffu, nd, i) * din;
            float4 hA = __ldg((const float4*)(hraw + (size_t)sA * 128) + lane);
            acc.x = fmaf(hA.x, nA, acc.x); acc.y = fmaf(hA.y, nA, acc.y);
            acc.z = fmaf(hA.z, nA, acc.z); acc.w = fmaf(hA.w, nA, acc.w);
        }
    }
    acc.x = fmaxf(acc.x + acc2.x, 0.0f); acc.y = fmaxf(acc.y + acc2.y, 0.0f);
    acc.z = fmaxf(acc.z + acc2.z, 0.0f); acc.w = fmaxf(acc.w + acc2.w, 0.0f);
    ((float4*)(out + (size_t)w * 128))[lane] = acc;
}

// ---------------- pull aggregation, C=64: warp per node, 2-way unrolled ----------
__global__ void k_pull64(const float* __restrict__ hraw, const float* __restrict__ b,
                         float* __restrict__ out) {
    int w = (blockIdx.x * blockDim.x + threadIdx.x) >> 5;
    if (w >= N_NODES) return;
    int lane = threadIdx.x & 31;
    float din = g_dinv[w];
    float2 h0 = __ldg((const float2*)(hraw + (size_t)w * 64) + lane);
    float2 bv = __ldg((const float2*)b + lane);
    float sl = din * din;
    float2 acc, acc2 = make_float2(0.f, 0.f);
    acc.x = fmaf(h0.x, sl, bv.x); acc.y = fmaf(h0.y, sl, bv.y);

    int s0 = g_off[w], s1 = g_off[w + 1];
    for (int j0 = s0; j0 < s1; j0 += 32) {
        int jj = j0 + lane;
        int cc = 0; float nd = 0.0f;
        if (jj < s1) { cc = g_col[jj]; nd = g_dinv[cc]; }
        int cnt = min(32, s1 - j0);
        int i = 0;
        for (; i + 2 <= cnt; i += 2) {
            int   sA = __shfl_sync(0xffffffffu, cc, i);
            float nA = __shfl_sync(0xffffffffu, nd, i) * din;
            int   sB = __shfl_sync(0xffffffffu, cc, i + 1);
            float nB = __shfl_sync(0xffffffffu, nd, i + 1) * din;
            float2 hA = __ldg((const float2*)(hraw + (size_t)sA * 64) + lane);
            float2 hB = __ldg((const float2*)(hraw + (size_t)sB * 64) + lane);
            acc.x  = fmaf(hA.x, nA, acc.x);  acc.y  = fmaf(hA.y, nA, acc.y);
            acc2.x = fmaf(hB.x, nB, acc2.x); acc2.y = fmaf(hB.y, nB, acc2.y);
        }
        if (i < cnt) {
            int   sA = __shfl_sync(0xffffffffu, cc, i);
            float nA = __shfl_sync(0xffffffffu, nd, i) * din;
            float2 hA = __ldg((const float2*)(hraw + (size_t)sA * 64) + lane);
            acc.x = fmaf(hA.x, nA, acc.x); acc.y = fmaf(hA.y, nA, acc.y);
        }
    }
    acc.x += acc2.x; acc.y += acc2.y;
    ((float2*)(out + (size_t)w * 64))[lane] = acc;
}

// ---------------- launch ----------------
extern "C" void kernel_launch(void* const* d_in, const int* in_sizes, int n_in,
                              void* d_out, int out_size) {
    const float* x  = (const float*)d_in[0];
    const int*   ei = (const int*)  d_in[1];
    const float* W1 = (const float*)d_in[2];
    const float* b1 = (const float*)d_in[3];
    const float* W2 = (const float*)d_in[4];
    const float* b2 = (const float*)d_in[5];

    const int* src = ei;
    const int* dst = ei + N_EDGES;

    float* out_h2 = (float*)d_out;                       // [N, 64]
    float* out_h1 = out_h2 + (size_t)N_NODES * OUT_DIM;  // [N, 128]

    void *p_h, *p_h2;
    cudaGetSymbolAddress(&p_h,  g_h);
    cudaGetSymbolAddress(&p_h2, g_h2);
    float* hbuf  = (float*)p_h;
    float* h2buf = (float*)p_h2;

    const int TB = 256;
    const int nblk_nodes = (N_NODES + TB - 1) / TB;      // 196
    const int nblk_edges = (N_EDGES + TB - 1) / TB;

    // degrees
    k_zero <<<nblk_nodes, TB>>>();
    k_count<<<nblk_edges, TB>>>(dst);

    // GEMM1 (lands in ncu capture slot)
    k_gemm<IN_DIM, HID_DIM, 32><<<(N_NODES + 63) / 64, 256>>>(x, W1, hbuf);

    // CSR build (+dinv fused into scan1)
    k_scan1<<<nblk_nodes, TB>>>();
    k_scan2<<<1, TB>>>(nblk_nodes);
    k_scan3<<<nblk_nodes, TB>>>();
    k_fill <<<nblk_edges, TB>>>(src, dst);

    // layer 1 aggregation (+bias/self-loop/ReLU fused)
    k_pull128<<<(N_NODES * 32 + TB - 1) / TB, TB>>>(hbuf, b1, out_h1);

    // layer 2
    k_gemm<HID_DIM, OUT_DIM, 16><<<(N_NODES + 127) / 128, 256>>>(out_h1, W2, h2buf);
    k_pull64<<<(N_NODES * 32 + TB - 1) / TB, TB>>>(h2buf, b2, out_h2);
}